// round 14
// baseline (speedup 1.0000x reference)
#include <cuda_runtime.h>
#include <cuda_bf16.h>
#include <math.h>
#include <stdint.h>

#define H    16
#define HD   128
#define HHD  2048   // H*HD
#define SEQ  2048
#define NT   4096   // B*S tokens
#define DIM  2048
#define QR   1536
#define KVR  512
#define NOPE 96
#define BH   32     // B*H
#define KVUP 4096   // QR + 512 + HHD

// ---------------- bf16 hi/lo scratch ----------------------------------------
__device__ __nv_bfloat16 g_x_h[(size_t)NT * DIM],  g_x_l[(size_t)NT * DIM];
__device__ __nv_bfloat16 g_qkv_h[(size_t)NT * 2048], g_qkv_l[(size_t)NT * 2048]; // [qlat|kv]
__device__ __nv_bfloat16 g_at_h[(size_t)NT * HHD], g_at_l[(size_t)NT * HHD];
// V in token layout (written by G3 epilogue), then transposed by vt_prep
__device__ __nv_bfloat16 g_vb_h[(size_t)NT * HHD], g_vb_l[(size_t)NT * HHD];
// attention operands, [BH][SEQ][HD] (Q,K) and [BH][HD][SEQ] (Vt)
__device__ __nv_bfloat16 g_qa_h[(size_t)BH * SEQ * HD], g_qa_l[(size_t)BH * SEQ * HD];
__device__ __nv_bfloat16 g_ka_h[(size_t)BH * SEQ * HD], g_ka_l[(size_t)BH * SEQ * HD];
__device__ __nv_bfloat16 g_vt_h[(size_t)BH * HD * SEQ], g_vt_l[(size_t)BH * HD * SEQ];
// weights, pre-transposed to [N,K]; wA = [wq_down | wkv_down], wB = [wn|wr|wv]
__device__ __nv_bfloat16 g_wA_h[(size_t)2048 * DIM],  g_wA_l[(size_t)2048 * DIM];
__device__ __nv_bfloat16 g_wqu_h[(size_t)HHD * QR],   g_wqu_l[(size_t)HHD * QR];
__device__ __nv_bfloat16 g_wB_h[(size_t)KVUP * KVR],  g_wB_l[(size_t)KVUP * KVR];
__device__ __nv_bfloat16 g_wo_h[(size_t)DIM * HHD],   g_wo_l[(size_t)DIM * HHD];

// ---------------- helpers ----------------------------------------------------
__device__ __forceinline__ uint32_t smem_u32(const void* p) {
  uint32_t a;
  asm("{ .reg .u64 t; cvta.to.shared.u64 t, %1; cvt.u32.u64 %0, t; }"
      : "=r"(a) : "l"(p));
  return a;
}
__device__ __forceinline__ void cp16(uint32_t dst, const void* src) {
  asm volatile("cp.async.cg.shared.global [%0], [%1], 16;"
               :: "r"(dst), "l"(src) : "memory");
}
__device__ __forceinline__ void cp_commit() {
  asm volatile("cp.async.commit_group;" ::: "memory");
}
__device__ __forceinline__ void mma16816(float* c, const uint32_t* a,
                                         const uint32_t* b) {
  asm volatile(
      "mma.sync.aligned.m16n8k16.row.col.f32.bf16.bf16.f32 "
      "{%0,%1,%2,%3}, {%4,%5,%6,%7}, {%8,%9}, {%0,%1,%2,%3};"
      : "+f"(c[0]), "+f"(c[1]), "+f"(c[2]), "+f"(c[3])
      : "r"(a[0]), "r"(a[1]), "r"(a[2]), "r"(a[3]), "r"(b[0]), "r"(b[1]));
}
__device__ __forceinline__ void ldsm_x4(uint32_t* r, uint32_t addr) {
  asm volatile(
      "ldmatrix.sync.aligned.m8n8.x4.shared.b16 {%0,%1,%2,%3}, [%4];"
      : "=r"(r[0]), "=r"(r[1]), "=r"(r[2]), "=r"(r[3]) : "r"(addr));
}
__device__ __forceinline__ uint32_t pack2bf(float a, float b) {
  __nv_bfloat162 t;
  t.x = __float2bfloat16(a);
  t.y = __float2bfloat16(b);
  return *reinterpret_cast<uint32_t*>(&t);
}
// write fp32 pair as hi/lo bf16 pairs
__device__ __forceinline__ void store_split(__nv_bfloat16* Hh,
                                            __nv_bfloat16* Ll, size_t idx,
                                            float v0, float v1) {
  float h0 = __bfloat162float(__float2bfloat16(v0));
  float h1 = __bfloat162float(__float2bfloat16(v1));
  *(uint32_t*)(Hh + idx) = pack2bf(v0, v1);
  *(uint32_t*)(Ll + idx) = pack2bf(v0 - h0, v1 - h1);
}

// ---------------- split conversion ------------------------------------------
__global__ void split_kernel(const float* __restrict__ in,
                             __nv_bfloat16* __restrict__ hi,
                             __nv_bfloat16* __restrict__ lo, int n4) {
  int i = blockIdx.x * blockDim.x + threadIdx.x;
  if (i >= n4) return;
  float4 v = ((const float4*)in)[i];
  __nv_bfloat16 h0 = __float2bfloat16(v.x);
  __nv_bfloat16 h1 = __float2bfloat16(v.y);
  __nv_bfloat16 h2 = __float2bfloat16(v.z);
  __nv_bfloat16 h3 = __float2bfloat16(v.w);
  __nv_bfloat16 l0 = __float2bfloat16(v.x - __bfloat162float(h0));
  __nv_bfloat16 l1 = __float2bfloat16(v.y - __bfloat162float(h1));
  __nv_bfloat16 l2 = __float2bfloat16(v.z - __bfloat162float(h2));
  __nv_bfloat16 l3 = __float2bfloat16(v.w - __bfloat162float(h3));
  uint2 hp, lp;
  hp.x = ((uint32_t)__bfloat16_as_ushort(h1) << 16) | __bfloat16_as_ushort(h0);
  hp.y = ((uint32_t)__bfloat16_as_ushort(h3) << 16) | __bfloat16_as_ushort(h2);
  lp.x = ((uint32_t)__bfloat16_as_ushort(l1) << 16) | __bfloat16_as_ushort(l0);
  lp.y = ((uint32_t)__bfloat16_as_ushort(l3) << 16) | __bfloat16_as_ushort(l2);
  ((uint2*)hi)[i] = hp;
  ((uint2*)lo)[i] = lp;
}

// W[Kd,Nd] -> Th/Tl[Nd,Kd] (bf16 hi/lo)
__global__ void tsplit_kernel(const float* __restrict__ W,
                              __nv_bfloat16* __restrict__ Th,
                              __nv_bfloat16* __restrict__ Tl, int Kd, int Nd) {
  __shared__ float t[32][33];
  int n0 = blockIdx.x * 32, k0 = blockIdx.y * 32;
  int tx = threadIdx.x, ty = threadIdx.y;
#pragma unroll
  for (int i = 0; i < 32; i += 8)
    t[ty + i][tx] = W[(size_t)(k0 + ty + i) * Nd + n0 + tx];
  __syncthreads();
#pragma unroll
  for (int i = 0; i < 32; i += 8) {
    float v = t[tx][ty + i];
    size_t o = (size_t)(n0 + ty + i) * Kd + k0 + tx;
    __nv_bfloat16 h = __float2bfloat16(v);
    Th[o] = h;
    Tl[o] = __float2bfloat16(v - __bfloat162float(h));
  }
}

// ---------------- mma.sync bf16-split GEMM, tile 128x128, fused epilogues ---
// modes: 0 = fp32 C[row][N]
//        1 = bf16 hi/lo split C[row][N]
//        2 = Q attention operand: rope(d>=96) + split + [BH][SEQ][HD]
//        3 = K/V: col<2048 -> K operand (nope|rope) [BH][SEQ][HD];
//                 col>=2048 -> V bf16 split [row][HHD]
#define MG_SMEM 81920

__device__ __forceinline__ void mg_load(uint32_t sb,
                                        const __nv_bfloat16* Ah,
                                        const __nv_bfloat16* Al,
                                        const __nv_bfloat16* Bh,
                                        const __nv_bfloat16* Bl,
                                        int lda, int ldb, int k0, int tid) {
#pragma unroll
  for (int i = 0; i < 2; i++) {
    int idx = tid + i * 256;
    int row = idx >> 2;
    int cw = (idx & 3) << 3;
    uint32_t d = sb + (uint32_t)(row * 80 + cw * 2);
    size_t ga = (size_t)row * lda + k0 + cw;
    size_t gb = (size_t)row * ldb + k0 + cw;
    cp16(d, Ah + ga);
    cp16(d + 10240, Al + ga);
    cp16(d + 20480, Bh + gb);
    cp16(d + 30720, Bl + gb);
  }
}

__global__ __launch_bounds__(256) void mma_gemm_kernel(
    const __nv_bfloat16* __restrict__ Ahi, const __nv_bfloat16* __restrict__ Alo,
    const __nv_bfloat16* __restrict__ Bhi, const __nv_bfloat16* __restrict__ Blo,
    float* __restrict__ Cf, __nv_bfloat16* __restrict__ Chi,
    __nv_bfloat16* __restrict__ Clo, __nv_bfloat16* __restrict__ Vbh,
    __nv_bfloat16* __restrict__ Vbl, const float* __restrict__ cosT,
    const float* __restrict__ sinT, int N, int K, int lda, int ldb, int mode) {
  extern __shared__ __nv_bfloat16 smh[];
  const uint32_t sbase = smem_u32(smh);
  const int tid = threadIdx.x;
  const int warp = tid >> 5, lane = tid & 31;
  const int wm = warp >> 2, wn = warp & 3;
  const int g = lane >> 2, tg = lane & 3;
  const size_t brow = (size_t)blockIdx.y * 128;
  const size_t bcol = (size_t)blockIdx.x * 128;
  const __nv_bfloat16* Ah = Ahi + brow * lda;
  const __nv_bfloat16* Al = Alo + brow * lda;
  const __nv_bfloat16* Bh = Bhi + bcol * ldb;
  const __nv_bfloat16* Bl = Blo + bcol * ldb;

  const int a_row = lane & 15, a_ko = (lane >> 4) << 3;
  const int b_row = ((lane >> 4) << 3) + (lane & 7);
  const int b_ko = ((lane >> 3) & 1) << 3;

  float c[4][4][4];
#pragma unroll
  for (int mi = 0; mi < 4; mi++)
#pragma unroll
    for (int ni = 0; ni < 4; ni++)
#pragma unroll
      for (int k = 0; k < 4; k++) c[mi][ni][k] = 0.f;

  const int nk = K >> 5;
  mg_load(sbase, Ah, Al, Bh, Bl, lda, ldb, 0, tid);
  cp_commit();

  for (int it = 0; it < nk; ++it) {
    if (it + 1 < nk) {
      mg_load(sbase + ((it + 1) & 1) * 40960, Ah, Al, Bh, Bl, lda, ldb,
              (it + 1) << 5, tid);
      cp_commit();
      asm volatile("cp.async.wait_group 1;" ::: "memory");
    } else {
      asm volatile("cp.async.wait_group 0;" ::: "memory");
    }
    __syncthreads();
    const uint32_t stgb = sbase + (it & 1) * 40960;
#pragma unroll
    for (int kk = 0; kk < 2; kk++) {
      uint32_t ah[4][4], al[4][4];
#pragma unroll
      for (int mi = 0; mi < 4; mi++) {
        uint32_t ar = stgb + (uint32_t)(((wm * 64 + mi * 16 + a_row) * 40 +
                                         kk * 16 + a_ko) * 2);
        ldsm_x4(ah[mi], ar);
        ldsm_x4(al[mi], ar + 10240);
      }
#pragma unroll
      for (int pi = 0; pi < 2; pi++) {
        uint32_t br = stgb + 20480 +
            (uint32_t)(((wn * 32 + pi * 16 + b_row) * 40 + kk * 16 + b_ko) * 2);
        uint32_t bhp[4], blp[4];
        ldsm_x4(bhp, br);
        ldsm_x4(blp, br + 10240);
#pragma unroll
        for (int mi = 0; mi < 4; mi++) {
          mma16816(c[mi][2 * pi], ah[mi], bhp);
          mma16816(c[mi][2 * pi], ah[mi], blp);
          mma16816(c[mi][2 * pi], al[mi], bhp);
          mma16816(c[mi][2 * pi + 1], ah[mi], bhp + 2);
          mma16816(c[mi][2 * pi + 1], ah[mi], blp + 2);
          mma16816(c[mi][2 * pi + 1], al[mi], bhp + 2);
        }
      }
    }
    __syncthreads();
  }

#pragma unroll
  for (int mi = 0; mi < 4; mi++) {
    size_t row = brow + wm * 64 + mi * 16 + g;
#pragma unroll
    for (int ni = 0; ni < 4; ni++) {
      int col = (int)bcol + wn * 32 + ni * 8 + tg * 2;
      float v0 = c[mi][ni][0], v1 = c[mi][ni][1];
      float v2 = c[mi][ni][2], v3 = c[mi][ni][3];
      if (mode == 0) {
        *(float2*)(Cf + row * N + col) = make_float2(v0, v1);
        *(float2*)(Cf + (row + 8) * N + col) = make_float2(v2, v3);
      } else if (mode == 1) {
        store_split(Chi, Clo, row * N + col, v0, v1);
        store_split(Chi, Clo, (row + 8) * N + col, v2, v3);
      } else if (mode == 2) {
        // Q operand: rope cols d>=96, relayout [BH][SEQ][HD]
        int s = (int)(row & (SEQ - 1));
        int bq = (int)(row >> 11);
        int h = col >> 7, d = col & 127;
        if (d >= NOPE) {
          int j = (d - NOPE) >> 1;
          float c0 = cosT[s * 16 + j], s0 = sinT[s * 16 + j];
          float r0 = v0 * c0 - v1 * s0, i0 = v0 * s0 + v1 * c0;
          v0 = r0; v1 = i0;
          float c1 = cosT[(s + 8) * 16 + j], s1 = sinT[(s + 8) * 16 + j];
          float r1 = v2 * c1 - v3 * s1, i1 = v2 * s1 + v3 * c1;
          v2 = r1; v3 = i1;
        }
        size_t dst = ((size_t)(bq * 16 + h) * SEQ + s) * HD + d;
        store_split(Chi, Clo, dst, v0, v1);
        store_split(Chi, Clo, dst + 8 * HD, v2, v3);
      } else {
        // mode 3: K assemble (nope|rope) or V split
        int s = (int)(row & (SEQ - 1));
        int bq = (int)(row >> 11);
        if (col >= 2048) {
          size_t dst = row * (size_t)HHD + (col - 2048);
          store_split(Vbh, Vbl, dst, v0, v1);
          store_split(Vbh, Vbl, dst + 8 * HHD, v2, v3);
        } else {
          int h, d;
          if (col < QR) {
            h = col / 96;
            d = col - h * 96;
          } else {
            int t = col - QR;
            h = t >> 5;
            int dd = t & 31;
            d = NOPE + dd;
            int j = dd >> 1;
            float c0 = cosT[s * 16 + j], s0 = sinT[s * 16 + j];
            float r0 = v0 * c0 - v1 * s0, i0 = v0 * s0 + v1 * c0;
            v0 = r0; v1 = i0;
            float c1 = cosT[(s + 8) * 16 + j], s1 = sinT[(s + 8) * 16 + j];
            float r1 = v2 * c1 - v3 * s1, i1 = v2 * s1 + v3 * c1;
            v2 = r1; v3 = i1;
          }
          size_t dst = ((size_t)(bq * 16 + h) * SEQ + s) * HD + d;
          store_split(Chi, Clo, dst, v0, v1);
          store_split(Chi, Clo, dst + 8 * HD, v2, v3);
        }
      }
    }
  }
}

// ---------------- v prep: bf16 transpose [tok][HHD] -> [BH][HD][SEQ] --------
__global__ void vt_prep_kernel(const __nv_bfloat16* __restrict__ vbh,
                               const __nv_bfloat16* __restrict__ vbl,
                               __nv_bfloat16* __restrict__ Vh,
                               __nv_bfloat16* __restrict__ Vl) {
  __shared__ __nv_bfloat16 th[32][34], tl[32][34];
  int bh = blockIdx.z, b = bh >> 4, h = bh & 15;
  int s0 = blockIdx.x * 32, d0 = blockIdx.y * 32;
  int tx = threadIdx.x, ty = threadIdx.y;
#pragma unroll
  for (int i = 0; i < 32; i += 8) {
    size_t src = ((size_t)(b * SEQ) + s0 + ty + i) * HHD + h * HD + d0 + tx;
    th[ty + i][tx] = vbh[src];
    tl[ty + i][tx] = vbl[src];
  }
  __syncthreads();
#pragma unroll
  for (int i = 0; i < 32; i += 8) {
    size_t o = ((size_t)bh * HD + d0 + ty + i) * SEQ + s0 + tx;
    Vh[o] = th[tx][ty + i];
    Vl[o] = tl[tx][ty + i];
  }
}

// ---------------- tensor-core flash attention (R13) --------------------------
#define FS_QL 17408
#define FS_K0 34816
#define FS_STG 35840
#define FS_KL 8704
#define FS_VH 17408
#define FLASH_MMA_SMEM 212992

__device__ __forceinline__ void flash_load_kv(
    uint32_t sb, const __nv_bfloat16* Kh, const __nv_bfloat16* Kl,
    const __nv_bfloat16* Vth, const __nv_bfloat16* Vtl, int kb, int stg,
    int tid) {
  uint32_t base = sb + (uint32_t)(FS_K0 + stg * FS_STG) * 2;
#pragma unroll
  for (int i = 0; i < 4; i++) {
    int idx = tid + i * 256;
    int r = idx >> 4, c = (idx & 15) << 3;
    uint32_t d = base + (uint32_t)(r * 136 + c) * 2;
    size_t gsrc = (size_t)(kb * 64 + r) * HD + c;
    cp16(d, Kh + gsrc);
    cp16(d + FS_KL * 2, Kl + gsrc);
  }
#pragma unroll
  for (int i = 0; i < 4; i++) {
    int idx = tid + i * 256;
    int r = idx >> 3, c = (idx & 7) << 3;
    uint32_t d = base + FS_VH * 2 + (uint32_t)(r * 72 + c) * 2;
    size_t gsrc = (size_t)r * SEQ + kb * 64 + c;
    cp16(d, Vth + gsrc);
    cp16(d + 9216 * 2, Vtl + gsrc);
  }
}

__global__ __launch_bounds__(256) void flash_mma_kernel(
    const __nv_bfloat16* __restrict__ Qh_, const __nv_bfloat16* __restrict__ Ql_,
    const __nv_bfloat16* __restrict__ Kh_, const __nv_bfloat16* __restrict__ Kl_,
    const __nv_bfloat16* __restrict__ Vh_, const __nv_bfloat16* __restrict__ Vl_,
    __nv_bfloat16* __restrict__ Oh, __nv_bfloat16* __restrict__ Ol) {
  extern __shared__ __nv_bfloat16 fs[];
  const uint32_t sb = smem_u32(fs);
  const int qb = gridDim.x - 1 - blockIdx.x;  // big tiles first
  const int bh = blockIdx.y;
  const int b = bh >> 4, h = bh & 15;
  const int tid = threadIdx.x, warp = tid >> 5, lane = tid & 31;
  const int g = lane >> 2, tg = lane & 3;
  const __nv_bfloat16* Qh = Qh_ + ((size_t)bh * SEQ + qb * 128) * HD;
  const __nv_bfloat16* Ql = Ql_ + ((size_t)bh * SEQ + qb * 128) * HD;
  const __nv_bfloat16* Kh = Kh_ + (size_t)bh * SEQ * HD;
  const __nv_bfloat16* Kl = Kl_ + (size_t)bh * SEQ * HD;
  const __nv_bfloat16* Vh = Vh_ + (size_t)bh * HD * SEQ;
  const __nv_bfloat16* Vl = Vl_ + (size_t)bh * HD * SEQ;

  const int a_row = lane & 15, a_ko = (lane >> 4) << 3;
  const int b_row = ((lane >> 4) << 3) + (lane & 7);
  const int b_ko = ((lane >> 3) & 1) << 3;

#pragma unroll
  for (int i = 0; i < 8; i++) {
    int idx = tid + i * 256;
    int r = idx >> 4, c = (idx & 15) << 3;
    uint32_t d = sb + (uint32_t)(r * 136 + c) * 2;
    cp16(d, Qh + (size_t)r * HD + c);
    cp16(d + FS_QL * 2, Ql + (size_t)r * HD + c);
  }
  flash_load_kv(sb, Kh, Kl, Vh, Vl, 0, 0, tid);
  cp_commit();

  float m0 = -1e30f, m1 = -1e30f, l0 = 0.f, l1 = 0.f;
  float o[16][4];
#pragma unroll
  for (int ni = 0; ni < 16; ni++)
#pragma unroll
    for (int k = 0; k < 4; k++) o[ni][k] = 0.f;

  const int nkb = 2 * qb + 2;
  const int rg0 = qb * 128 + warp * 16 + g;
  const int rg1 = rg0 + 8;
  const float scale = 0.08838834764831843f;

  for (int kb = 0; kb < nkb; kb++) {
    if (kb + 1 < nkb) {
      flash_load_kv(sb, Kh, Kl, Vh, Vl, kb + 1, (kb + 1) & 1, tid);
      cp_commit();
      asm volatile("cp.async.wait_group 1;" ::: "memory");
    } else {
      asm volatile("cp.async.wait_group 0;" ::: "memory");
    }
    __syncthreads();
    const uint32_t ksb = sb + (uint32_t)(FS_K0 + (kb & 1) * FS_STG) * 2;
    const uint32_t vsb = ksb + FS_VH * 2;

    float c[8][4];
#pragma unroll
    for (int ni = 0; ni < 8; ni++)
#pragma unroll
      for (int k = 0; k < 4; k++) c[ni][k] = 0.f;
#pragma unroll
    for (int kk = 0; kk < 8; kk++) {
      uint32_t ah[4], al[4];
      uint32_t qa = sb + (uint32_t)(((warp * 16 + a_row) * 136 +
                                     kk * 16 + a_ko) * 2);
      ldsm_x4(ah, qa);
      ldsm_x4(al, qa + FS_QL * 2);
#pragma unroll
      for (int pi = 0; pi < 4; pi++) {
        uint32_t ka = ksb + (uint32_t)(((pi * 16 + b_row) * 136 +
                                        kk * 16 + b_ko) * 2);
        uint32_t bhp[4], blp[4];
        ldsm_x4(bhp, ka);
        ldsm_x4(blp, ka + FS_KL * 2);
        mma16816(c[2 * pi], ah, bhp);
        mma16816(c[2 * pi], al, bhp);
        mma16816(c[2 * pi], ah, blp);
        mma16816(c[2 * pi + 1], ah, bhp + 2);
        mma16816(c[2 * pi + 1], al, bhp + 2);
        mma16816(c[2 * pi + 1], ah, blp + 2);
      }
    }

    const bool msk = (kb >= 2 * qb);
    float mx0 = -1e30f, mx1 = -1e30f;
#pragma unroll
    for (int ni = 0; ni < 8; ni++) {
      int cg = kb * 64 + ni * 8 + tg * 2;
      float t0 = c[ni][0] * scale, t1 = c[ni][1] * scale;
      float t2 = c[ni][2] * scale, t3 = c[ni][3] * scale;
      if (msk) {
        if (cg > rg0) t0 = -1e30f;
        if (cg + 1 > rg0) t1 = -1e30f;
        if (cg > rg1) t2 = -1e30f;
        if (cg + 1 > rg1) t3 = -1e30f;
      }
      c[ni][0] = t0; c[ni][1] = t1; c[ni][2] = t2; c[ni][3] = t3;
      mx0 = fmaxf(mx0, fmaxf(t0, t1));
      mx1 = fmaxf(mx1, fmaxf(t2, t3));
    }
    mx0 = fmaxf(mx0, __shfl_xor_sync(0xffffffffu, mx0, 1));
    mx0 = fmaxf(mx0, __shfl_xor_sync(0xffffffffu, mx0, 2));
    mx1 = fmaxf(mx1, __shfl_xor_sync(0xffffffffu, mx1, 1));
    mx1 = fmaxf(mx1, __shfl_xor_sync(0xffffffffu, mx1, 2));

    float mn0 = fmaxf(m0, mx0), mn1 = fmaxf(m1, mx1);
    float corr0 = __expf(m0 - mn0), corr1 = __expf(m1 - mn1);
    m0 = mn0; m1 = mn1;
    float s0 = 0.f, s1 = 0.f;
#pragma unroll
    for (int ni = 0; ni < 8; ni++) {
      c[ni][0] = __expf(c[ni][0] - mn0);
      c[ni][1] = __expf(c[ni][1] - mn0);
      c[ni][2] = __expf(c[ni][2] - mn1);
      c[ni][3] = __expf(c[ni][3] - mn1);
      s0 += c[ni][0] + c[ni][1];
      s1 += c[ni][2] + c[ni][3];
    }
    s0 += __shfl_xor_sync(0xffffffffu, s0, 1);
    s0 += __shfl_xor_sync(0xffffffffu, s0, 2);
    s1 += __shfl_xor_sync(0xffffffffu, s1, 1);
    s1 += __shfl_xor_sync(0xffffffffu, s1, 2);
    l0 = l0 * corr0 + s0;
    l1 = l1 * corr1 + s1;

#pragma unroll
    for (int ni = 0; ni < 16; ni++) {
      o[ni][0] *= corr0; o[ni][1] *= corr0;
      o[ni][2] *= corr1; o[ni][3] *= corr1;
    }

#pragma unroll
    for (int kc = 0; kc < 4; kc++) {
      float p00 = c[2 * kc][0], p01 = c[2 * kc][1];
      float p02 = c[2 * kc][2], p03 = c[2 * kc][3];
      float p10 = c[2 * kc + 1][0], p11 = c[2 * kc + 1][1];
      float p12 = c[2 * kc + 1][2], p13 = c[2 * kc + 1][3];
      uint32_t ap[4], apl[4];
      ap[0] = pack2bf(p00, p01);
      ap[1] = pack2bf(p02, p03);
      ap[2] = pack2bf(p10, p11);
      ap[3] = pack2bf(p12, p13);
      float h00 = __bfloat162float(__float2bfloat16(p00));
      float h01 = __bfloat162float(__float2bfloat16(p01));
      float h02 = __bfloat162float(__float2bfloat16(p02));
      float h03 = __bfloat162float(__float2bfloat16(p03));
      float h10 = __bfloat162float(__float2bfloat16(p10));
      float h11 = __bfloat162float(__float2bfloat16(p11));
      float h12 = __bfloat162float(__float2bfloat16(p12));
      float h13 = __bfloat162float(__float2bfloat16(p13));
      apl[0] = pack2bf(p00 - h00, p01 - h01);
      apl[1] = pack2bf(p02 - h02, p03 - h03);
      apl[2] = pack2bf(p10 - h10, p11 - h11);
      apl[3] = pack2bf(p12 - h12, p13 - h13);
#pragma unroll
      for (int pi = 0; pi < 8; pi++) {
        uint32_t va = vsb + (uint32_t)(((pi * 16 + b_row) * 72 +
                                        kc * 16 + b_ko) * 2);
        uint32_t bv[4], bvl[4];
        ldsm_x4(bv, va);
        ldsm_x4(bvl, va + 18432);
        mma16816(o[2 * pi], ap, bv);
        mma16816(o[2 * pi], apl, bv);
        mma16816(o[2 * pi], ap, bvl);
        mma16816(o[2 * pi + 1], ap, bv + 2);
        mma16816(o[2 * pi + 1], apl, bv + 2);
        mma16816(o[2 * pi + 1], ap, bvl + 2);
      }
    }
    __syncthreads();
  }

  const float inv0 = 1.f / l0, inv1 = 1.f / l1;
  const size_t row0 = (size_t)b * SEQ + qb * 128 + warp * 16 + g;
#pragma unroll
  for (int ni = 0; ni < 16; ni++) {
    int col = h * HD + ni * 8 + tg * 2;
    store_split(Oh, Ol, row0 * HHD + col, o[ni][0] * inv0, o[ni][1] * inv0);
    store_split(Oh, Ol, (row0 + 8) * HHD + col, o[ni][2] * inv1,
                o[ni][3] * inv1);
  }
}

// ---------------- launch -----------------------------------------------------
#define SYM(p, s)                          \
  do {                                     \
    void* _t;                              \
    cudaGetSymbolAddress(&_t, s);          \
    p = (decltype(p))_t;                   \
  } while (0)

extern "C" void kernel_launch(void* const* d_in, const int* in_sizes, int n_in,
                              void* d_out, int out_size) {
  const float* x = (const float*)d_in[0];
  const float* cosT = (const float*)d_in[1];
  const float* sinT = (const float*)d_in[2];
  const float* wq_down = (const float*)d_in[3];
  const float* wq_up = (const float*)d_in[4];
  const float* wkv_down = (const float*)d_in[5];
  const float* w_nope = (const float*)d_in[6];
  const float* w_rope = (const float*)d_in[7];
  const float* w_val = (const float*)d_in[8];
  const float* wo = (const float*)d_in[9];
  float* out = (float*)d_out;

  __nv_bfloat16 *xh, *xl, *qkvh, *qkvl, *ath, *atl, *vbh, *vbl;
  __nv_bfloat16 *qah, *qal, *kah, *kal, *vth, *vtl;
  __nv_bfloat16 *wAh, *wAl, *wquh, *wqul, *wBh, *wBl, *woh, *wol;
  SYM(xh, g_x_h);   SYM(xl, g_x_l);
  SYM(qkvh, g_qkv_h); SYM(qkvl, g_qkv_l);
  SYM(ath, g_at_h); SYM(atl, g_at_l);
  SYM(vbh, g_vb_h); SYM(vbl, g_vb_l);
  SYM(qah, g_qa_h); SYM(qal, g_qa_l); SYM(kah, g_ka_h); SYM(kal, g_ka_l);
  SYM(vth, g_vt_h); SYM(vtl, g_vt_l);
  SYM(wAh, g_wA_h); SYM(wAl, g_wA_l); SYM(wquh, g_wqu_h); SYM(wqul, g_wqu_l);
  SYM(wBh, g_wB_h); SYM(wBl, g_wB_l); SYM(woh, g_wo_h);  SYM(wol, g_wo_l);

  cudaFuncSetAttribute(mma_gemm_kernel,
                       cudaFuncAttributeMaxDynamicSharedMemorySize, MG_SMEM);
  cudaFuncSetAttribute(flash_mma_kernel,
                       cudaFuncAttributeMaxDynamicSharedMemorySize,
                       FLASH_MMA_SMEM);

  dim3 tsb(32, 8);
  // input/weight conversions (wA = [wq_down | wkv_down], wB = [wn|wr|wv])
  split_kernel<<<(NT * DIM / 4) / 256, 256>>>(x, xh, xl, NT * DIM / 4);
  tsplit_kernel<<<dim3(QR / 32, DIM / 32), tsb>>>(wq_down, wAh, wAl, DIM, QR);
  tsplit_kernel<<<dim3(KVR / 32, DIM / 32), tsb>>>(
      wkv_down, wAh + (size_t)QR * DIM, wAl + (size_t)QR * DIM, DIM, KVR);
  tsplit_kernel<<<dim3(HHD / 32, QR / 32), tsb>>>(wq_up, wquh, wqul, QR, HHD);
  tsplit_kernel<<<dim3(QR / 32, KVR / 32), tsb>>>(w_nope, wBh, wBl, KVR, QR);
  tsplit_kernel<<<dim3(512 / 32, KVR / 32), tsb>>>(
      w_rope, wBh + (size_t)QR * KVR, wBl + (size_t)QR * KVR, KVR, 512);
  tsplit_kernel<<<dim3(HHD / 32, KVR / 32), tsb>>>(
      w_val, wBh + (size_t)2048 * KVR, wBl + (size_t)2048 * KVR, KVR, HHD);
  tsplit_kernel<<<dim3(DIM / 32, HHD / 32), tsb>>>(wo, woh, wol, HHD, DIM);

  // G1: x @ [wq_down|wkv_down] -> qkv hi/lo bf16 [NT, 2048]
  mma_gemm_kernel<<<dim3(2048 / 128, NT / 128), 256, MG_SMEM>>>(
      xh, xl, wAh, wAl, nullptr, qkvh, qkvl, nullptr, nullptr, nullptr,
      nullptr, 2048, DIM, DIM, DIM, 1);
  // G2: qlat @ wq_up -> flash Q operand (rope+split+relayout fused)
  mma_gemm_kernel<<<dim3(HHD / 128, NT / 128), 256, MG_SMEM>>>(
      qkvh, qkvl, wquh, wqul, nullptr, qah, qal, nullptr, nullptr, cosT,
      sinT, HHD, QR, 2048, QR, 2);
  // G3: kv @ [wn|wr|wv] -> flash K operand + V bf16 split
  mma_gemm_kernel<<<dim3(KVUP / 128, NT / 128), 256, MG_SMEM>>>(
      qkvh + QR, qkvl + QR, wBh, wBl, nullptr, kah, kal, vbh, vbl, cosT,
      sinT, KVUP, KVR, 2048, KVR, 3);

  // V transpose (bf16 -> [BH][HD][SEQ])
  vt_prep_kernel<<<dim3(SEQ / 32, HD / 32, BH), tsb>>>(vbh, vbl, vth, vtl);

  // attention (writes bf16 hi/lo directly)
  flash_mma_kernel<<<dim3(SEQ / 128, BH), 256, FLASH_MMA_SMEM>>>(
      qah, qal, kah, kal, vth, vtl, ath, atl);

  // G4: attn @ wo -> out fp32
  mma_gemm_kernel<<<dim3(DIM / 128, NT / 128), 256, MG_SMEM>>>(
      ath, atl, woh, wol, out, nullptr, nullptr, nullptr, nullptr, nullptr,
      nullptr, DIM, HHD, HHD, HHD, 0);
}